// round 4
// baseline (speedup 1.0000x reference)
#include <cuda_runtime.h>

// CBOW negative-sampling loss:
//   src[b]   = sum_c ctx_emb[contexts[b,c]]                       (B x D)
//   pred[b,k]= dot(src[b], neg_emb[focus[b,k]])                   (B x K)
//   bce      = w * (softplus(pred) - pred*y)
//   out      = mean_b( sum_k bce / sum_k w )
//
// B=16384, C=10, K=8, D=128, VOCAB=100000. Output: 1 float.
//
// R4: latency-bound regime -> occupancy push. 40-reg cap (6 blocks/SM, 75%
// theoretical occ) with gathers batched (2x5 ctx, 2x4 neg) to fit the reg
// budget; epilogue reduced to group-stride shfls.

#define NB     16384
#define NC     10
#define NK     8
#define NDIM   128
#define WPB    8          // warps per block (1 warp = 1 example)

__global__ void cbow_zero_out(float* __restrict__ out) {
    if (threadIdx.x == 0) out[0] = 0.0f;
}

// Butterfly step merging two reduction trees: lanes with (lane & s)==0 carry
// x's partial sum onward, the others carry y's.
__device__ __forceinline__ float merge2(float x, float y, int s, int lane) {
    float xs = __shfl_xor_sync(0xffffffffu, x, s);
    float ys = __shfl_xor_sync(0xffffffffu, y, s);
    return (lane & s) ? (y + ys) : (x + xs);
}

__global__ __launch_bounds__(WPB * 32, 6)
void cbow_kernel(const int*   __restrict__ contexts,   // [B, C]
                 const int*   __restrict__ focus,      // [B, K]
                 const float* __restrict__ weight,     // [B, K]
                 const float* __restrict__ labels,     // [B, K]
                 const float* __restrict__ ctx_emb,    // [VOCAB, D]
                 const float* __restrict__ neg_emb,    // [VOCAB, D]
                 float*       __restrict__ out)
{
    const int warp = threadIdx.x >> 5;
    const int lane = threadIdx.x & 31;
    const int b    = blockIdx.x * WPB + warp;

    const float4* cb4 = reinterpret_cast<const float4*>(ctx_emb) + lane;
    const float4* nb4 = reinterpret_cast<const float4*>(neg_emb) + lane;
    const int2*   c2  = reinterpret_cast<const int2*>(contexts + b * NC);

    float4 src = make_float4(0.f, 0.f, 0.f, 0.f);

    // ---- ctx batch 0: rows 0..4 (<=5 float4 + 5 idx live) ----
    {
        int2 ca = __ldg(c2 + 0), cbi = __ldg(c2 + 1), cc = __ldg(c2 + 2);
        float4 e0 = __ldg(cb4 + ca.x  * (NDIM / 4));
        float4 e1 = __ldg(cb4 + ca.y  * (NDIM / 4));
        float4 e2 = __ldg(cb4 + cbi.x * (NDIM / 4));
        float4 e3 = __ldg(cb4 + cbi.y * (NDIM / 4));
        float4 e4 = __ldg(cb4 + cc.x  * (NDIM / 4));
        src.x = e0.x + e1.x + e2.x + e3.x + e4.x;
        src.y = e0.y + e1.y + e2.y + e3.y + e4.y;
        src.z = e0.z + e1.z + e2.z + e3.z + e4.z;
        src.w = e0.w + e1.w + e2.w + e3.w + e4.w;
    }
    // ---- ctx batch 1: rows 5..9 ----
    {
        int2 cc = __ldg(c2 + 2), cd = __ldg(c2 + 3), ce = __ldg(c2 + 4);
        float4 e0 = __ldg(cb4 + cc.y * (NDIM / 4));
        float4 e1 = __ldg(cb4 + cd.x * (NDIM / 4));
        float4 e2 = __ldg(cb4 + cd.y * (NDIM / 4));
        float4 e3 = __ldg(cb4 + ce.x * (NDIM / 4));
        float4 e4 = __ldg(cb4 + ce.y * (NDIM / 4));
        src.x += e0.x + e1.x + e2.x + e3.x + e4.x;
        src.y += e0.y + e1.y + e2.y + e3.y + e4.y;
        src.z += e0.z + e1.z + e2.z + e3.z + e4.z;
        src.w += e0.w + e1.w + e2.w + e3.w + e4.w;
    }

    // ---- neg gathers + partial dots, 2 batches of 4 ----
    const int4* f4 = reinterpret_cast<const int4*>(focus + b * NK);
    float p[NK];
    #pragma unroll
    for (int half = 0; half < 2; half++) {
        int4 fi = __ldg(f4 + half);
        float4 t0 = __ldg(nb4 + fi.x * (NDIM / 4));
        float4 t1 = __ldg(nb4 + fi.y * (NDIM / 4));
        float4 t2 = __ldg(nb4 + fi.z * (NDIM / 4));
        float4 t3 = __ldg(nb4 + fi.w * (NDIM / 4));
        p[half * 4 + 0] = src.x * t0.x + src.y * t0.y + src.z * t0.z + src.w * t0.w;
        p[half * 4 + 1] = src.x * t1.x + src.y * t1.y + src.z * t1.z + src.w * t1.w;
        p[half * 4 + 2] = src.x * t2.x + src.y * t2.y + src.z * t2.z + src.w * t2.w;
        p[half * 4 + 3] = src.x * t3.x + src.y * t3.y + src.z * t3.z + src.w * t3.w;
    }

    // ---- merged 8-way warp reduction (16 shfl) ----
    float m01 = merge2(p[0], p[1], 16, lane);
    float m23 = merge2(p[2], p[3], 16, lane);
    float m45 = merge2(p[4], p[5], 16, lane);
    float m67 = merge2(p[6], p[7], 16, lane);
    float n03 = merge2(m01, m23, 8, lane);
    float n47 = merge2(m45, m67, 8, lane);
    float q   = merge2(n03, n47, 4, lane);
    q += __shfl_xor_sync(0xffffffffu, q, 2);
    q += __shfl_xor_sync(0xffffffffu, q, 1);
    // q = pred[b, k], k = bitrev3(lane>>2), replicated across each 4-lane group.

    const int g = lane >> 2;
    const int k = ((g & 1) << 2) | (g & 2) | (g >> 2);   // bitrev3

    float w = __ldg(weight + b * NK + k);
    float y = __ldg(labels + b * NK + k);

    // softplus via MUFU: logaddexp(0,q) = max(q,0) + log(1 + exp(-|q|))
    float sp  = fmaxf(q, 0.f) + __logf(1.f + __expf(-fabsf(q)));
    float bce = w * (sp - q * y);

    // Values are identical within each 4-lane group -> cross-group sums need
    // only strides 16/8/4; the uniform x4 factor cancels in the ratio.
    float ls = bce, ws = w;
    #pragma unroll
    for (int s = 16; s >= 4; s >>= 1) {
        ls += __shfl_xor_sync(0xffffffffu, ls, s);
        ws += __shfl_xor_sync(0xffffffffu, ws, s);
    }
    float contrib = ls / ws * (1.0f / (float)NB);

    __shared__ float sh[WPB];
    if (lane == 0) sh[warp] = contrib;
    __syncthreads();
    if (threadIdx.x == 0) {
        float s = 0.f;
        #pragma unroll
        for (int i = 0; i < WPB; i++) s += sh[i];
        atomicAdd(out, s);
    }
}

extern "C" void kernel_launch(void* const* d_in, const int* in_sizes, int n_in,
                              void* d_out, int out_size) {
    const int*   contexts = (const int*)  d_in[0];   // [B, C] int32
    const int*   focus    = (const int*)  d_in[1];   // [B, K] int32
    const float* weight   = (const float*)d_in[2];   // [B, K] f32
    const float* labels   = (const float*)d_in[3];   // [B, K] f32
    const float* ctx_emb  = (const float*)d_in[4];   // [VOCAB, D] f32
    const float* neg_emb  = (const float*)d_in[5];   // [VOCAB, D] f32
    float* out = (float*)d_out;

    cbow_zero_out<<<1, 32>>>(out);
    cbow_kernel<<<NB / WPB, WPB * 32>>>(contexts, focus, weight, labels,
                                        ctx_emb, neg_emb, out);
}